// round 13
// baseline (speedup 1.0000x reference)
#include <cuda_runtime.h>
#include <cuda_fp16.h>
#include <cstdint>
#include <math.h>

#define S_TOK 4096
#define HID   1024
#define FF    4096
#define NE    8
#define CAP   1280
#define TWOF  8192

// pair-index permutation within 8-pair (16-half) blocks: [0,4,1,5,2,6,3,7]
#define PERM8(k) (((k) & ~7) | ((((k) & 3)) << 1) | (((k) >> 2) & 1))

__device__ int   g_e1[S_TOK], g_e2[S_TOK];
__device__ float g_p1[S_TOK], g_p2[S_TOK];
__device__ int   g_slot1[S_TOK], g_slot2[S_TOK];
__device__ float g_fw1[S_TOK], g_fw2[S_TOK];
__device__ int   g_slot_token[NE * CAP];
__device__ int   g_cnt[NE];

__device__ __half g_TOK [(size_t)S_TOK * HID];      // fp16, H pair-permuted
__device__ __half g_WGt [(size_t)NE * TWOF * HID];  // [E][2F][H] fp16, H perm
__device__ __half g_WUt [(size_t)NE * FF * HID];    // [E][F][H]  fp16, H perm
__device__ __half g_WDt [(size_t)NE * HID * FF];    // [E][H][F]  fp16, F perm
__device__ __half g_ACT [(size_t)NE * CAP * FF];    // fp16, F pair-permuted
__device__ float  g_EOUT[(size_t)NE * CAP * HID];

// ---------- helpers ----------
__device__ __forceinline__ void mma_f16(float* d, const uint32_t* a, const uint32_t* b) {
    asm("mma.sync.aligned.m16n8k16.row.col.f32.f16.f16.f32 "
        "{%0,%1,%2,%3}, {%4,%5,%6,%7}, {%8,%9}, {%0,%1,%2,%3};"
        : "+f"(d[0]), "+f"(d[1]), "+f"(d[2]), "+f"(d[3])
        : "r"(a[0]), "r"(a[1]), "r"(a[2]), "r"(a[3]), "r"(b[0]), "r"(b[1]));
}
__device__ __forceinline__ void cp16(uint32_t sa, const void* ga, bool ok) {
    int sz = ok ? 16 : 0;
    asm volatile("cp.async.cg.shared.global [%0], [%1], 16, %2;\n" :: "r"(sa), "l"(ga), "r"(sz));
}
#define CP_COMMIT() asm volatile("cp.async.commit_group;\n" ::: "memory")
template <int N> __device__ __forceinline__ void cp_wait() {
    asm volatile("cp.async.wait_group %0;" :: "n"(N) : "memory");
}

// ---------- 1) router (emits fp16, pair-permuted tokens) ----------
__global__ void __launch_bounds__(256) router_kernel(const float* __restrict__ hid,
                                                     const float* __restrict__ gw) {
    int s = blockIdx.x, tid = threadIdx.x;
    __shared__ float red[NE][256];
    float acc[NE];
#pragma unroll
    for (int e = 0; e < NE; e++) acc[e] = 0.f;
    const float* row = hid + (size_t)s * HID;
    __half2* tdst = (__half2*)(g_TOK + (size_t)s * HID);
#pragma unroll
    for (int it = 0; it < 2; it++) {
        int p = tid + it * 256;              // pair index (h = 2p, 2p+1)
        float2 x = *(const float2*)(row + 2 * p);
        tdst[PERM8(p)] = __floats2half2_rn(x.x, x.y);
        float4 lo = *(const float4*)(gw + (size_t)(2 * p) * NE);
        float4 hi4 = *(const float4*)(gw + (size_t)(2 * p) * NE + 4);
        acc[0] += x.x*lo.x; acc[1] += x.x*lo.y; acc[2] += x.x*lo.z; acc[3] += x.x*lo.w;
        acc[4] += x.x*hi4.x; acc[5] += x.x*hi4.y; acc[6] += x.x*hi4.z; acc[7] += x.x*hi4.w;
        lo = *(const float4*)(gw + (size_t)(2 * p + 1) * NE);
        hi4 = *(const float4*)(gw + (size_t)(2 * p + 1) * NE + 4);
        acc[0] += x.y*lo.x; acc[1] += x.y*lo.y; acc[2] += x.y*lo.z; acc[3] += x.y*lo.w;
        acc[4] += x.y*hi4.x; acc[5] += x.y*hi4.y; acc[6] += x.y*hi4.z; acc[7] += x.y*hi4.w;
    }
#pragma unroll
    for (int e = 0; e < NE; e++) red[e][tid] = acc[e];
    __syncthreads();
    for (int st = 128; st > 0; st >>= 1) {
        if (tid < st)
#pragma unroll
            for (int e = 0; e < NE; e++) red[e][tid] += red[e][tid + st];
        __syncthreads();
    }
    if (tid == 0) {
        float l[NE], p[NE];
#pragma unroll
        for (int e = 0; e < NE; e++) l[e] = red[e][0];
        float m = l[0];
#pragma unroll
        for (int e = 1; e < NE; e++) m = fmaxf(m, l[e]);
        float se = 0.f;
#pragma unroll
        for (int e = 0; e < NE; e++) { p[e] = expf(l[e] - m); se += p[e]; }
        float inv = 1.f / se;
#pragma unroll
        for (int e = 0; e < NE; e++) p[e] *= inv;
        int t1 = 0; float b1 = p[0];
        for (int e = 1; e < NE; e++) if (p[e] > b1) { b1 = p[e]; t1 = e; }
        int t2 = (t1 == 0) ? 1 : 0; float b2 = p[t2];
        for (int e = 0; e < NE; e++) if (e != t1 && p[e] > b2) { b2 = p[e]; t2 = e; }
        g_e1[s] = t1; g_e2[s] = t2; g_p1[s] = b1; g_p2[s] = b2;
    }
}

// ---------- 2) scan ----------
__global__ void __launch_bounds__(256) scan_kernel() {
    __shared__ unsigned char se1[S_TOK], se2[S_TOK];
    __shared__ int c1[256][NE], c2[256][NE];
    int tid = threadIdx.x;
    for (int i = tid; i < NE * CAP; i += 256) g_slot_token[i] = -1;
    for (int i = tid; i < S_TOK; i += 256) {
        se1[i] = (unsigned char)g_e1[i];
        se2[i] = (unsigned char)g_e2[i];
    }
    __syncthreads();
    int lc1[NE], lc2[NE];
#pragma unroll
    for (int e = 0; e < NE; e++) { lc1[e] = 0; lc2[e] = 0; }
    for (int j = 0; j < 16; j++) {
        int s = tid * 16 + j;
        lc1[se1[s]]++; lc2[se2[s]]++;
    }
#pragma unroll
    for (int e = 0; e < NE; e++) { c1[tid][e] = lc1[e]; c2[tid][e] = lc2[e]; }
    __syncthreads();
    if (tid < NE) {
        int e = tid, run = 0;
        for (int t = 0; t < 256; t++) { int v = c1[t][e]; c1[t][e] = run; run += v; }
        int run2 = run;  // rank2 base = PRE-capacity top1 total (matches reference)
        for (int t = 0; t < 256; t++) { int v = c2[t][e]; c2[t][e] = run2; run2 += v; }
        g_cnt[e] = run2 < CAP ? run2 : CAP;
    }
    __syncthreads();
    int o1[NE], o2[NE];
#pragma unroll
    for (int e = 0; e < NE; e++) { o1[e] = c1[tid][e]; o2[e] = c2[tid][e]; }
    for (int j = 0; j < 16; j++) {
        int s = tid * 16 + j;
        int e1 = se1[s], e2 = se2[s];
        int r1 = o1[e1]++, r2 = o2[e2]++;
        if (r1 < CAP) { int sl = e1*CAP+r1; g_slot1[s]=sl; g_slot_token[sl]=s; g_fw1[s]=g_p1[s]; }
        else          { g_slot1[s]=0; g_fw1[s]=0.f; }
        if (r2 < CAP) { int sl = e2*CAP+r2; g_slot2[s]=sl; g_slot_token[sl]=s; g_fw2[s]=g_p2[s]; }
        else          { g_slot2[s]=0; g_fw2[s]=0.f; }
    }
}

// ---------- weight transpose: [E][K][N] fp32 -> [E][N][K] fp16, K pair-permuted ----------
__global__ void __launch_bounds__(256) transpose_kernel(const float* __restrict__ src,
                                                        __half* __restrict__ dst,
                                                        int K, int N) {
    __shared__ float t[32][33];
    int e = blockIdx.z;
    src += (size_t)e * K * N;
    dst += (size_t)e * N * K;
    int n0 = blockIdx.x * 32, k0 = blockIdx.y * 32;
    int tx = threadIdx.x & 31, ty = threadIdx.x >> 5;   // 32 x 8
#pragma unroll
    for (int j = 0; j < 4; j++)
        t[ty + j * 8][tx] = src[(size_t)(k0 + ty + j * 8) * N + n0 + tx];
    __syncthreads();
    int kp = k0 + ((PERM8(tx >> 1) << 1) | (tx & 1));
#pragma unroll
    for (int j = 0; j < 4; j++)
        dst[(size_t)(n0 + ty + j * 8) * K + kp] = __float2half_rn(t[tx][ty + j * 8]);
}

// ========== 3) fused GEMM1 + SwiGLU (fp16 m16n8k16, 2-stage k64) ==========
// Block 128m x 64f, 512 thr (16 warps 4m x 4n), warp tile 32m x 16f per matrix.
// Stage: A 128 rows x 160B + B 3x64 rows x 160B = 51200B; 2 stages = 100KB -> 2 CTAs/SM.
#define G1_ROWB 160
#define G1_ABUF (128 * G1_ROWB)          // 20480 B
#define G1_BMAT (64 * G1_ROWB)           // 10240 B
#define G1_STG  (G1_ABUF + 3 * G1_BMAT)  // 51200 B
#define G1_DS   (2 * G1_STG)             // 102400 B
#define G1_NK   (HID / 64)               // 16

__global__ void __launch_bounds__(512, 2) gemm1_kernel() {
    extern __shared__ char raw[];
    __shared__ int stok[128];

    const int e = blockIdx.z, m0 = blockIdx.x * 128, f0 = blockIdx.y * 64;
    if (m0 >= g_cnt[e]) return;
    const int tid = threadIdx.x;

    if (tid < 128) stok[tid] = g_slot_token[e * CAP + m0 + tid];
    __syncthreads();

    const __half* W0 = g_WGt + (size_t)e * TWOF * HID + (size_t)f0 * HID;        // x1 rows
    const __half* W1 = g_WGt + (size_t)e * TWOF * HID + (size_t)(FF + f0) * HID; // x2 rows
    const __half* W2 = g_WUt + (size_t)e * FF * HID + (size_t)f0 * HID;          // u rows

    const uint32_t smb = (uint32_t)__cvta_generic_to_shared(raw);

    // A: 2 chunks/thread (rows ar, ar+64), 8 chunks(16B)/row
    const int ar = tid >> 3, ac = tid & 7;
    const int t0 = stok[ar], t1 = stok[ar + 64];
    const bool aok0 = (t0 >= 0), aok1 = (t1 >= 0);
    const __half* as0 = g_TOK + (size_t)(t0 < 0 ? 0 : t0) * HID + ac * 8;
    const __half* as1 = g_TOK + (size_t)(t1 < 0 ? 0 : t1) * HID + ac * 8;
    const uint32_t ad0 = ar * G1_ROWB + ac * 16;
    const uint32_t ad1 = (ar + 64) * G1_ROWB + ac * 16;
    // B: 3 chunks/thread (row ar<64? same mapping: row br = tid>>3 covers 0..63)
    const int br = ar;   // 0..63 valid rows only for tid<512 -> br 0..63 when tid<512? tid>>3 in 0..63 ✓
    const uint32_t bdst = G1_ABUF + br * G1_ROWB + ac * 16;
    const __half* ws[3] = { W0 + (size_t)br * HID + ac * 8,
                            W1 + (size_t)br * HID + ac * 8,
                            W2 + (size_t)br * HID + ac * 8 };

#define G1_LD(st, kt) do {                                                     \
    uint32_t _sb = smb + (uint32_t)(st) * G1_STG;                              \
    cp16(_sb + ad0, as0 + (kt), aok0);                                         \
    cp16(_sb + ad1, as1 + (kt), aok1);                                         \
    _Pragma("unroll") for (int j = 0; j < 3; j++)                              \
        cp16(_sb + bdst + j * G1_BMAT, ws[j] + (kt), true);                    \
    CP_COMMIT(); } while (0)

    float acc[3][2][2][4];
#pragma unroll
    for (int j = 0; j < 3; j++)
#pragma unroll
        for (int mt = 0; mt < 2; mt++)
#pragma unroll
            for (int nt = 0; nt < 2; nt++)
#pragma unroll
                for (int i = 0; i < 4; i++) acc[j][mt][nt][i] = 0.f;

    const int warp = tid >> 5, lane = tid & 31;
    const int warp_m = warp >> 2, warp_n = warp & 3;   // 4m x 4n
    const int g = lane >> 2, c = lane & 3;

    G1_LD(0, 0);

    for (int i = 0; i < G1_NK; i++) {
        cp_wait<0>();
        __syncthreads();
        if (i + 1 < G1_NK) G1_LD((i + 1) & 1, (i + 1) * 64);

        const char* Ab = raw + (i & 1) * G1_STG;
        const char* Bb = Ab + G1_ABUF;
#pragma unroll
        for (int s = 0; s < 4; s++) {          // 4 x k16
            const int off = s * 32 + c * 8;
            uint32_t a[2][4];
#pragma unroll
            for (int mt = 0; mt < 2; mt++) {
                int r0 = warp_m * 32 + mt * 16;
                uint2 v0 = *(const uint2*)(Ab + (r0 + g) * G1_ROWB + off);
                uint2 v1 = *(const uint2*)(Ab + (r0 + g + 8) * G1_ROWB + off);
                a[mt][0] = v0.x; a[mt][1] = v1.x; a[mt][2] = v0.y; a[mt][3] = v1.y;
            }
#pragma unroll
            for (int j = 0; j < 3; j++) {
                uint32_t b[2][2];
#pragma unroll
                for (int nt = 0; nt < 2; nt++) {
                    int n = warp_n * 16 + nt * 8 + g;
                    uint2 vb = *(const uint2*)(Bb + j * G1_BMAT + n * G1_ROWB + off);
                    b[nt][0] = vb.x; b[nt][1] = vb.y;
                }
#pragma unroll
                for (int mt = 0; mt < 2; mt++)
#pragma unroll
                    for (int nt = 0; nt < 2; nt++)
                        mma_f16(acc[j][mt][nt], a[mt], b[nt]);
            }
        }
    }

    // epilogue: act = x1*silu(x2)*u -> fp16, F pair-permuted
#pragma unroll
    for (int mt = 0; mt < 2; mt++)
#pragma unroll
        for (int nt = 0; nt < 2; nt++) {
            int row = m0 + warp_m * 32 + mt * 16 + g;
            int colp = (f0 + warp_n * 16 + nt * 8 + c * 2) >> 1;   // pair index
            float o[4];
#pragma unroll
            for (int i = 0; i < 4; i++) {
                float x1 = acc[0][mt][nt][i];
                float x2 = acc[1][mt][nt][i];
                float u  = acc[2][mt][nt][i];
                o[i] = x1 * (x2 / (1.f + __expf(-x2))) * u;
            }
            ((__half2*)(g_ACT + ((size_t)e * CAP + row) * FF))[PERM8(colp)] =
                __floats2half2_rn(o[0], o[1]);
            ((__half2*)(g_ACT + ((size_t)e * CAP + row + 8) * FF))[PERM8(colp)] =
                __floats2half2_rn(o[2], o[3]);
        }
#undef G1_LD
}

// ========== 4) GEMM2: ACT x w_down^T -> EOUT (fp16, 2-stage k64) ==========
// Block 128m x 128n, 256 thr (8 warps 2m x 4n), warp tile 64m x 32n.
#define G2_ROWB 160
#define G2_ABUF (128 * G2_ROWB)          // 20480 B
#define G2_BBUF (128 * G2_ROWB)          // 20480 B
#define G2_STG  (G2_ABUF + G2_BBUF)      // 40960 B
#define G2_DS   (2 * G2_STG)             // 81920 B
#define G2_NK   (FF / 64)

__global__ void __launch_bounds__(256, 2) gemm2_kernel() {
    extern __shared__ char raw[];

    const int e = blockIdx.z, m0 = blockIdx.x * 128, n0 = blockIdx.y * 128;
    if (m0 >= g_cnt[e]) return;
    const int tid = threadIdx.x;

    const __half* A = g_ACT + (size_t)(e * CAP + m0) * FF;
    const __half* B = g_WDt + (size_t)e * HID * FF + (size_t)n0 * FF;
    float* Cout = g_EOUT + (size_t)e * CAP * HID + n0;

    const uint32_t smb = (uint32_t)__cvta_generic_to_shared(raw);
    const int ar = tid >> 3, ac = tid & 7;   // rows ar + q*32, 8 chunks/row

#define G2_LD(st, kt) do {                                                       \
    uint32_t _sb = smb + (uint32_t)(st) * G2_STG;                                \
    _Pragma("unroll") for (int q = 0; q < 4; q++)                                \
        cp16(_sb + (ar + q * 32) * G2_ROWB + ac * 16,                            \
             A + (size_t)(ar + q * 32) * FF + (kt) + ac * 8, true);              \
    _Pragma("unroll") for (int q = 0; q < 4; q++)                                \
        cp16(_sb + G2_ABUF + (ar + q * 32) * G2_ROWB + ac * 16,                  \
             B + (size_t)(ar + q * 32) * FF + (kt) + ac * 8, true);              \
    CP_COMMIT(); } while (0)

    float acc[4][4][4];
#pragma unroll
    for (int mt = 0; mt < 4; mt++)
#pragma unroll
        for (int nt = 0; nt < 4; nt++)
#pragma unroll
            for (int i = 0; i < 4; i++) acc[mt][nt][i] = 0.f;

    const int warp = tid >> 5, lane = tid & 31;
    const int warp_m = warp >> 2, warp_n = warp & 3;   // 2m x 4n
    const int g = lane >> 2, c = lane & 3;

    G2_LD(0, 0);

    for (int i = 0; i < G2_NK; i++) {
        cp_wait<0>();
        __syncthreads();
        if (i + 1 < G2_NK) G2_LD((i + 1) & 1, (i + 1) * 64);

        const char* Ab = raw + (i & 1) * G2_STG;
        const char* Bb = Ab + G2_ABUF;
#pragma unroll
        for (int s = 0; s < 4; s++) {
            const int off = s * 32 + c * 8;
            uint32_t a[4][4];
#pragma unroll
            for (int mt = 0; mt < 4; mt++) {
                int r0 = warp_m * 64 + mt * 16;
                uint2 v0 = *(const uint2*)(Ab + (r0 + g) * G2_ROWB + off);
                uint2 v1 = *(const uint2*)(Ab + (r0 + g + 8) * G2_ROWB + off);
                a[mt][0] = v0.x; a[mt][1] = v1.x; a[mt][2] = v0.y; a[mt][3] = v1.y;
            }
#pragma unroll
            for (int nt = 0; nt < 4; nt++) {
                int n = warp_n * 32 + nt * 8 + g;
                uint2 vb = *(const uint2*)(Bb + n * G2_ROWB + off);
                uint32_t b[2] = { vb.x, vb.y };
#pragma unroll
                for (int mt = 0; mt < 4; mt++)
                    mma_f16(acc[mt][nt], a[mt], b);
            }
        }
    }

#pragma unroll
    for (int mt = 0; mt < 4; mt++)
#pragma unroll
        for (int nt = 0; nt < 4; nt++) {
            int row = m0 + warp_m * 64 + mt * 16 + g;
            int col = warp_n * 32 + nt * 8 + c * 2;
            *(float2*)(Cout + (size_t)row * HID + col)       = make_float2(acc[mt][nt][0], acc[mt][nt][1]);
            *(float2*)(Cout + (size_t)(row + 8) * HID + col) = make_float2(acc[mt][nt][2], acc[mt][nt][3]);
        }
#undef G2_LD
}

// ---------- 5) combine ----------
__global__ void __launch_bounds__(256) combine_kernel(float* __restrict__ out) {
    int s = blockIdx.x, h = threadIdx.x * 4;
    int sl1 = g_slot1[s], sl2 = g_slot2[s];
    float w1 = g_fw1[s], w2 = g_fw2[s];
    float4 a = *(const float4*)(g_EOUT + (size_t)sl1 * HID + h);
    float4 b = *(const float4*)(g_EOUT + (size_t)sl2 * HID + h);
    float4 o;
    o.x = w1*a.x + w2*b.x; o.y = w1*a.y + w2*b.y;
    o.z = w1*a.z + w2*b.z; o.w = w1*a.w + w2*b.w;
    *(float4*)(out + (size_t)s * HID + h) = o;
}

extern "C" void kernel_launch(void* const* d_in, const int* in_sizes, int n_in,
                              void* d_out, int out_size) {
    const float* hid = (const float*)d_in[0];
    const float* gw  = (const float*)d_in[1];
    const float* wg  = (const float*)d_in[2];
    const float* wu  = (const float*)d_in[3];
    const float* wd  = (const float*)d_in[4];
    float* out = (float*)d_out;

    cudaFuncSetAttribute(gemm1_kernel, cudaFuncAttributeMaxDynamicSharedMemorySize, G1_DS);
    cudaFuncSetAttribute(gemm2_kernel, cudaFuncAttributeMaxDynamicSharedMemorySize, G2_DS);

    __half* wgt; cudaGetSymbolAddress((void**)&wgt, g_WGt);
    __half* wut; cudaGetSymbolAddress((void**)&wut, g_WUt);
    __half* wdt; cudaGetSymbolAddress((void**)&wdt, g_WDt);

    transpose_kernel<<<dim3(TWOF / 32, HID / 32, NE), 256>>>(wg, wgt, HID, TWOF);
    transpose_kernel<<<dim3(FF / 32, HID / 32, NE), 256>>>(wu, wut, HID, FF);
    transpose_kernel<<<dim3(HID / 32, FF / 32, NE), 256>>>(wd, wdt, FF, HID);
    router_kernel<<<S_TOK, 256>>>(hid, gw);
    scan_kernel<<<1, 256>>>();
    gemm1_kernel<<<dim3(CAP / 128, FF / 64, NE), 512, G1_DS>>>();
    gemm2_kernel<<<dim3(CAP / 128, HID / 128, NE), 256, G2_DS>>>();
    combine_kernel<<<S_TOK, 256>>>(out);
}

// round 14
// speedup vs baseline: 1.4143x; 1.4143x over previous
#include <cuda_runtime.h>
#include <cuda_fp16.h>
#include <cstdint>
#include <math.h>

#define S_TOK 4096
#define HID   1024
#define FF    4096
#define NE    8
#define CAP   1280
#define TWOF  8192

// pair-index permutation within 8-pair (16-half) blocks: [0,4,1,5,2,6,3,7]
#define PERM8(k) (((k) & ~7) | ((((k) & 3)) << 1) | (((k) >> 2) & 1))

__device__ int   g_e1[S_TOK], g_e2[S_TOK];
__device__ float g_p1[S_TOK], g_p2[S_TOK];
__device__ int   g_slot1[S_TOK], g_slot2[S_TOK];
__device__ float g_fw1[S_TOK], g_fw2[S_TOK];
__device__ int   g_slot_token[NE * CAP];
__device__ int   g_cnt[NE];

__device__ __half g_TOK [(size_t)S_TOK * HID];      // fp16, H pair-permuted
__device__ __half g_WGt [(size_t)NE * TWOF * HID];  // [E][2F][H] fp16, H perm
__device__ __half g_WUt [(size_t)NE * FF * HID];    // [E][F][H]  fp16, H perm
__device__ __half g_WDt [(size_t)NE * HID * FF];    // [E][H][F]  fp16, F perm
__device__ __half g_ACT [(size_t)NE * CAP * FF];    // fp16, F pair-permuted
__device__ float  g_EOUT[(size_t)NE * CAP * HID];

// ---------- helpers ----------
__device__ __forceinline__ void mma_f16(float* d, const uint32_t* a, const uint32_t* b) {
    asm("mma.sync.aligned.m16n8k16.row.col.f32.f16.f16.f32 "
        "{%0,%1,%2,%3}, {%4,%5,%6,%7}, {%8,%9}, {%0,%1,%2,%3};"
        : "+f"(d[0]), "+f"(d[1]), "+f"(d[2]), "+f"(d[3])
        : "r"(a[0]), "r"(a[1]), "r"(a[2]), "r"(a[3]), "r"(b[0]), "r"(b[1]));
}
__device__ __forceinline__ void cp16(uint32_t sa, const void* ga, bool ok) {
    int sz = ok ? 16 : 0;
    asm volatile("cp.async.cg.shared.global [%0], [%1], 16, %2;\n" :: "r"(sa), "l"(ga), "r"(sz));
}
#define CP_COMMIT() asm volatile("cp.async.commit_group;\n" ::: "memory")
template <int N> __device__ __forceinline__ void cp_wait() {
    asm volatile("cp.async.wait_group %0;" :: "n"(N) : "memory");
}

// ---------- 1) router (emits fp16, pair-permuted tokens) ----------
__global__ void __launch_bounds__(256) router_kernel(const float* __restrict__ hid,
                                                     const float* __restrict__ gw) {
    int s = blockIdx.x, tid = threadIdx.x;
    __shared__ float red[NE][256];
    float acc[NE];
#pragma unroll
    for (int e = 0; e < NE; e++) acc[e] = 0.f;
    const float* row = hid + (size_t)s * HID;
    __half2* tdst = (__half2*)(g_TOK + (size_t)s * HID);
#pragma unroll
    for (int it = 0; it < 2; it++) {
        int p = tid + it * 256;              // pair index (h = 2p, 2p+1)
        float2 x = *(const float2*)(row + 2 * p);
        tdst[PERM8(p)] = __floats2half2_rn(x.x, x.y);
        float4 lo = *(const float4*)(gw + (size_t)(2 * p) * NE);
        float4 hi4 = *(const float4*)(gw + (size_t)(2 * p) * NE + 4);
        acc[0] += x.x*lo.x; acc[1] += x.x*lo.y; acc[2] += x.x*lo.z; acc[3] += x.x*lo.w;
        acc[4] += x.x*hi4.x; acc[5] += x.x*hi4.y; acc[6] += x.x*hi4.z; acc[7] += x.x*hi4.w;
        lo = *(const float4*)(gw + (size_t)(2 * p + 1) * NE);
        hi4 = *(const float4*)(gw + (size_t)(2 * p + 1) * NE + 4);
        acc[0] += x.y*lo.x; acc[1] += x.y*lo.y; acc[2] += x.y*lo.z; acc[3] += x.y*lo.w;
        acc[4] += x.y*hi4.x; acc[5] += x.y*hi4.y; acc[6] += x.y*hi4.z; acc[7] += x.y*hi4.w;
    }
#pragma unroll
    for (int e = 0; e < NE; e++) red[e][tid] = acc[e];
    __syncthreads();
    for (int st = 128; st > 0; st >>= 1) {
        if (tid < st)
#pragma unroll
            for (int e = 0; e < NE; e++) red[e][tid] += red[e][tid + st];
        __syncthreads();
    }
    if (tid == 0) {
        float l[NE], p[NE];
#pragma unroll
        for (int e = 0; e < NE; e++) l[e] = red[e][0];
        float m = l[0];
#pragma unroll
        for (int e = 1; e < NE; e++) m = fmaxf(m, l[e]);
        float se = 0.f;
#pragma unroll
        for (int e = 0; e < NE; e++) { p[e] = expf(l[e] - m); se += p[e]; }
        float inv = 1.f / se;
#pragma unroll
        for (int e = 0; e < NE; e++) p[e] *= inv;
        int t1 = 0; float b1 = p[0];
        for (int e = 1; e < NE; e++) if (p[e] > b1) { b1 = p[e]; t1 = e; }
        int t2 = (t1 == 0) ? 1 : 0; float b2 = p[t2];
        for (int e = 0; e < NE; e++) if (e != t1 && p[e] > b2) { b2 = p[e]; t2 = e; }
        g_e1[s] = t1; g_e2[s] = t2; g_p1[s] = b1; g_p2[s] = b2;
    }
}

// ---------- 2) scan ----------
__global__ void __launch_bounds__(256) scan_kernel() {
    __shared__ unsigned char se1[S_TOK], se2[S_TOK];
    __shared__ int c1[256][NE], c2[256][NE];
    int tid = threadIdx.x;
    for (int i = tid; i < NE * CAP; i += 256) g_slot_token[i] = -1;
    for (int i = tid; i < S_TOK; i += 256) {
        se1[i] = (unsigned char)g_e1[i];
        se2[i] = (unsigned char)g_e2[i];
    }
    __syncthreads();
    int lc1[NE], lc2[NE];
#pragma unroll
    for (int e = 0; e < NE; e++) { lc1[e] = 0; lc2[e] = 0; }
    for (int j = 0; j < 16; j++) {
        int s = tid * 16 + j;
        lc1[se1[s]]++; lc2[se2[s]]++;
    }
#pragma unroll
    for (int e = 0; e < NE; e++) { c1[tid][e] = lc1[e]; c2[tid][e] = lc2[e]; }
    __syncthreads();
    if (tid < NE) {
        int e = tid, run = 0;
        for (int t = 0; t < 256; t++) { int v = c1[t][e]; c1[t][e] = run; run += v; }
        int run2 = run;  // rank2 base = PRE-capacity top1 total (matches reference)
        for (int t = 0; t < 256; t++) { int v = c2[t][e]; c2[t][e] = run2; run2 += v; }
        g_cnt[e] = run2 < CAP ? run2 : CAP;
    }
    __syncthreads();
    int o1[NE], o2[NE];
#pragma unroll
    for (int e = 0; e < NE; e++) { o1[e] = c1[tid][e]; o2[e] = c2[tid][e]; }
    for (int j = 0; j < 16; j++) {
        int s = tid * 16 + j;
        int e1 = se1[s], e2 = se2[s];
        int r1 = o1[e1]++, r2 = o2[e2]++;
        if (r1 < CAP) { int sl = e1*CAP+r1; g_slot1[s]=sl; g_slot_token[sl]=s; g_fw1[s]=g_p1[s]; }
        else          { g_slot1[s]=0; g_fw1[s]=0.f; }
        if (r2 < CAP) { int sl = e2*CAP+r2; g_slot2[s]=sl; g_slot_token[sl]=s; g_fw2[s]=g_p2[s]; }
        else          { g_slot2[s]=0; g_fw2[s]=0.f; }
    }
}

// ---------- weight transpose: [E][K][N] fp32 -> [E][N][K] fp16, K pair-permuted ----------
__global__ void __launch_bounds__(256) transpose_kernel(const float* __restrict__ src,
                                                        __half* __restrict__ dst,
                                                        int K, int N) {
    __shared__ float t[32][33];
    int e = blockIdx.z;
    src += (size_t)e * K * N;
    dst += (size_t)e * N * K;
    int n0 = blockIdx.x * 32, k0 = blockIdx.y * 32;
    int tx = threadIdx.x & 31, ty = threadIdx.x >> 5;   // 32 x 8
#pragma unroll
    for (int j = 0; j < 4; j++)
        t[ty + j * 8][tx] = src[(size_t)(k0 + ty + j * 8) * N + n0 + tx];
    __syncthreads();
    int kp = k0 + ((PERM8(tx >> 1) << 1) | (tx & 1));
#pragma unroll
    for (int j = 0; j < 4; j++)
        dst[(size_t)(n0 + ty + j * 8) * K + kp] = __float2half_rn(t[tx][ty + j * 8]);
}

// ========== 3) fused GEMM1 + SwiGLU (fp16 m16n8k16, asymmetric A2/B3 pipeline) ==========
// Block 64m x 64f, 256 thr (8 warps 2m x 4n), warp tile 32m x 16f per matrix.
// A: 2 buffers of 64 rows x 160B; B: 3 buffers of 3x64 rows x 160B. 112.6KB -> 2 CTAs/SM.
#define G1_ROWB 160
#define G1_ABUF 10240                    // 64*160
#define G1_BMAT 10240                    // 64*160
#define G1_BSTG 30720                    // 3 mats
#define G1_BOFF 20480                    // after 2 A buffers
#define G1_DS   (G1_BOFF + 3 * G1_BSTG)  // 112640 B
#define G1_NK   (HID / 64)               // 16

__global__ void __launch_bounds__(256, 2) gemm1_kernel() {
    extern __shared__ char raw[];
    __shared__ int stok[64];

    const int e = blockIdx.z, m0 = blockIdx.x * 64, f0 = blockIdx.y * 64;
    if (m0 >= g_cnt[e]) return;
    const int tid = threadIdx.x;

    if (tid < 64) stok[tid] = g_slot_token[e * CAP + m0 + tid];
    __syncthreads();

    const __half* W0 = g_WGt + (size_t)e * TWOF * HID + (size_t)f0 * HID;        // x1 rows
    const __half* W1 = g_WGt + (size_t)e * TWOF * HID + (size_t)(FF + f0) * HID; // x2 rows
    const __half* W2 = g_WUt + (size_t)e * FF * HID + (size_t)f0 * HID;          // u rows

    const uint32_t smb = (uint32_t)__cvta_generic_to_shared(raw);

    // A: 2 chunks/thread (rows ar, ar+32), 8 chunks(16B)/row
    const int ar = tid >> 3, ac = tid & 7;
    const int t0 = stok[ar], t1 = stok[ar + 32];
    const bool aok0 = (t0 >= 0), aok1 = (t1 >= 0);
    const __half* as0 = g_TOK + (size_t)(t0 < 0 ? 0 : t0) * HID + ac * 8;
    const __half* as1 = g_TOK + (size_t)(t1 < 0 ? 0 : t1) * HID + ac * 8;
    const uint32_t ad0 = ar * G1_ROWB + ac * 16;
    const uint32_t ad1 = (ar + 32) * G1_ROWB + ac * 16;
    // B: rows ar, ar+32 per matrix
    const uint32_t bd0 = ar * G1_ROWB + ac * 16;
    const uint32_t bd1 = (ar + 32) * G1_ROWB + ac * 16;
    const __half* ws0[3] = { W0 + (size_t)ar * HID + ac * 8,
                             W1 + (size_t)ar * HID + ac * 8,
                             W2 + (size_t)ar * HID + ac * 8 };
    const __half* ws1[3] = { W0 + (size_t)(ar + 32) * HID + ac * 8,
                             W1 + (size_t)(ar + 32) * HID + ac * 8,
                             W2 + (size_t)(ar + 32) * HID + ac * 8 };

#define G1_LDA(st, kt) do {                                                    \
    uint32_t _sb = smb + (uint32_t)(st) * G1_ABUF;                             \
    cp16(_sb + ad0, as0 + (kt), aok0);                                         \
    cp16(_sb + ad1, as1 + (kt), aok1);                                         \
    CP_COMMIT(); } while (0)
#define G1_LDB(st, kt) do {                                                    \
    uint32_t _sb = smb + G1_BOFF + (uint32_t)(st) * G1_BSTG;                   \
    _Pragma("unroll") for (int j = 0; j < 3; j++) {                            \
        cp16(_sb + bd0 + j * G1_BMAT, ws0[j] + (kt), true);                    \
        cp16(_sb + bd1 + j * G1_BMAT, ws1[j] + (kt), true);                    \
    }                                                                          \
    CP_COMMIT(); } while (0)

    float acc[3][2][2][4];
#pragma unroll
    for (int j = 0; j < 3; j++)
#pragma unroll
        for (int mt = 0; mt < 2; mt++)
#pragma unroll
            for (int nt = 0; nt < 2; nt++)
#pragma unroll
                for (int i = 0; i < 4; i++) acc[j][mt][nt][i] = 0.f;

    const int warp = tid >> 5, lane = tid & 31;
    const int warp_m = warp >> 2, warp_n = warp & 3;   // 2m x 4n
    const int g = lane >> 2, c = lane & 3;

    // prologue: B(0), A(0), B(1)  -> pending groups {B0, A0, B1}
    G1_LDB(0, 0);
    G1_LDA(0, 0);
    G1_LDB(1, 64);

    int bs = 0;   // B stage of iter i
    for (int i = 0; i < G1_NK; i++) {
        cp_wait<1>();          // completes B(i), A(i); leaves B(i+1) in flight
        __syncthreads();
        if (i + 1 < G1_NK) G1_LDA((i + 1) & 1, (i + 1) * 64); else CP_COMMIT();
        {
            int ip2 = i + 2;
            int bs2 = bs + 2; if (bs2 >= 3) bs2 -= 3;
            if (ip2 < G1_NK) G1_LDB(bs2, ip2 * 64); else CP_COMMIT();
        }

        const char* Ab = raw + (i & 1) * G1_ABUF;
        const char* Bb = raw + G1_BOFF + bs * G1_BSTG;
        if (++bs == 3) bs = 0;
#pragma unroll
        for (int s = 0; s < 4; s++) {          // 4 x k16
            const int off = s * 32 + c * 8;
            uint32_t a[2][4];
#pragma unroll
            for (int mt = 0; mt < 2; mt++) {
                int r0 = warp_m * 32 + mt * 16;
                uint2 v0 = *(const uint2*)(Ab + (r0 + g) * G1_ROWB + off);
                uint2 v1 = *(const uint2*)(Ab + (r0 + g + 8) * G1_ROWB + off);
                a[mt][0] = v0.x; a[mt][1] = v1.x; a[mt][2] = v0.y; a[mt][3] = v1.y;
            }
#pragma unroll
            for (int j = 0; j < 3; j++) {
                uint32_t b[2][2];
#pragma unroll
                for (int nt = 0; nt < 2; nt++) {
                    int n = warp_n * 16 + nt * 8 + g;
                    uint2 vb = *(const uint2*)(Bb + j * G1_BMAT + n * G1_ROWB + off);
                    b[nt][0] = vb.x; b[nt][1] = vb.y;
                }
#pragma unroll
                for (int mt = 0; mt < 2; mt++)
#pragma unroll
                    for (int nt = 0; nt < 2; nt++)
                        mma_f16(acc[j][mt][nt], a[mt], b[nt]);
            }
        }
    }

    // epilogue: act = x1*silu(x2)*u -> fp16, F pair-permuted
#pragma unroll
    for (int mt = 0; mt < 2; mt++)
#pragma unroll
        for (int nt = 0; nt < 2; nt++) {
            int row = m0 + warp_m * 32 + mt * 16 + g;
            int colp = (f0 + warp_n * 16 + nt * 8 + c * 2) >> 1;   // pair index
            float o[4];
#pragma unroll
            for (int i = 0; i < 4; i++) {
                float x1 = acc[0][mt][nt][i];
                float x2 = acc[1][mt][nt][i];
                float u  = acc[2][mt][nt][i];
                o[i] = x1 * (x2 / (1.f + __expf(-x2))) * u;
            }
            ((__half2*)(g_ACT + ((size_t)e * CAP + row) * FF))[PERM8(colp)] =
                __floats2half2_rn(o[0], o[1]);
            ((__half2*)(g_ACT + ((size_t)e * CAP + row + 8) * FF))[PERM8(colp)] =
                __floats2half2_rn(o[2], o[3]);
        }
#undef G1_LDA
#undef G1_LDB
}

// ========== 4) GEMM2: ACT x w_down^T -> EOUT (fp16, asymmetric A2/B3 pipeline) ==========
// Block 128m x 128n, 256 thr (8 warps 2m x 4n), warp tile 64m x 32n. 100KB -> 2 CTAs/SM.
#define G2_ROWB 160
#define G2_ABUF 20480                    // 128*160
#define G2_BBUF 20480
#define G2_BOFF 40960
#define G2_DS   (G2_BOFF + 3 * G2_BBUF)  // 102400 B
#define G2_NK   (FF / 64)                // 64

__global__ void __launch_bounds__(256, 2) gemm2_kernel() {
    extern __shared__ char raw[];

    const int e = blockIdx.z, m0 = blockIdx.x * 128, n0 = blockIdx.y * 128;
    if (m0 >= g_cnt[e]) return;
    const int tid = threadIdx.x;

    const __half* A = g_ACT + (size_t)(e * CAP + m0) * FF;
    const __half* B = g_WDt + (size_t)e * HID * FF + (size_t)n0 * FF;
    float* Cout = g_EOUT + (size_t)e * CAP * HID + n0;

    const uint32_t smb = (uint32_t)__cvta_generic_to_shared(raw);
    const int ar = tid >> 3, ac = tid & 7;   // rows ar + q*32, 8 chunks/row

#define G2_LDA(st, kt) do {                                                      \
    uint32_t _sb = smb + (uint32_t)(st) * G2_ABUF;                               \
    _Pragma("unroll") for (int q = 0; q < 4; q++)                                \
        cp16(_sb + (ar + q * 32) * G2_ROWB + ac * 16,                            \
             A + (size_t)(ar + q * 32) * FF + (kt) + ac * 8, true);              \
    CP_COMMIT(); } while (0)
#define G2_LDB(st, kt) do {                                                      \
    uint32_t _sb = smb + G2_BOFF + (uint32_t)(st) * G2_BBUF;                     \
    _Pragma("unroll") for (int q = 0; q < 4; q++)                                \
        cp16(_sb + (ar + q * 32) * G2_ROWB + ac * 16,                            \
             B + (size_t)(ar + q * 32) * FF + (kt) + ac * 8, true);              \
    CP_COMMIT(); } while (0)

    float acc[4][4][4];
#pragma unroll
    for (int mt = 0; mt < 4; mt++)
#pragma unroll
        for (int nt = 0; nt < 4; nt++)
#pragma unroll
            for (int i = 0; i < 4; i++) acc[mt][nt][i] = 0.f;

    const int warp = tid >> 5, lane = tid & 31;
    const int warp_m = warp >> 2, warp_n = warp & 3;   // 2m x 4n
    const int g = lane >> 2, c = lane & 3;

    // prologue: B(0), A(0), B(1)
    G2_LDB(0, 0);
    G2_LDA(0, 0);
    G2_LDB(1, 64);

    int bs = 0;
    for (int i = 0; i < G2_NK; i++) {
        cp_wait<1>();
        __syncthreads();
        if (i + 1 < G2_NK) G2_LDA((i + 1) & 1, (i + 1) * 64); else CP_COMMIT();
        {
            int ip2 = i + 2;
            int bs2 = bs + 2; if (bs2 >= 3) bs2 -= 3;
            if (ip2 < G2_NK) G2_LDB(bs2, ip2 * 64); else CP_COMMIT();
        }

        const char* Ab = raw + (i & 1) * G2_ABUF;
        const char* Bb = raw + G2_BOFF + bs * G2_BBUF;
        if (++bs == 3) bs = 0;
#pragma unroll
        for (int s = 0; s < 4; s++) {
            const int off = s * 32 + c * 8;
            uint32_t a[4][4];
#pragma unroll
            for (int mt = 0; mt < 4; mt++) {
                int r0 = warp_m * 64 + mt * 16;
                uint2 v0 = *(const uint2*)(Ab + (r0 + g) * G2_ROWB + off);
                uint2 v1 = *(const uint2*)(Ab + (r0 + g + 8) * G2_ROWB + off);
                a[mt][0] = v0.x; a[mt][1] = v1.x; a[mt][2] = v0.y; a[mt][3] = v1.y;
            }
#pragma unroll
            for (int nt = 0; nt < 4; nt++) {
                int n = warp_n * 32 + nt * 8 + g;
                uint2 vb = *(const uint2*)(Bb + n * G2_ROWB + off);
                uint32_t b[2] = { vb.x, vb.y };
#pragma unroll
                for (int mt = 0; mt < 4; mt++)
                    mma_f16(acc[mt][nt], a[mt], b);
            }
        }
    }

#pragma unroll
    for (int mt = 0; mt < 4; mt++)
#pragma unroll
        for (int nt = 0; nt < 4; nt++) {
            int row = m0 + warp_m * 64 + mt * 16 + g;
            int col = warp_n * 32 + nt * 8 + c * 2;
            *(float2*)(Cout + (size_t)row * HID + col)       = make_float2(acc[mt][nt][0], acc[mt][nt][1]);
            *(float2*)(Cout + (size_t)(row + 8) * HID + col) = make_float2(acc[mt][nt][2], acc[mt][nt][3]);
        }
#undef G2_LDA
#undef G2_LDB
}

// ---------- 5) combine ----------
__global__ void __launch_bounds__(256) combine_kernel(float* __restrict__ out) {
    int s = blockIdx.x, h = threadIdx.x * 4;
    int sl1 = g_slot1[s], sl2 = g_slot2[s];
    float w1 = g_fw1[s], w2 = g_fw2[s];
    float4 a = *(const float4*)(g_EOUT + (size_t)sl1 * HID + h);
    float4 b = *(const float4*)(g_EOUT + (size_t)sl2 * HID + h);
    float4 o;
    o.x = w1*a.x + w2*b.x; o.y = w1*a.y + w2*b.y;
    o.z = w1*a.z + w2*b.z; o.w = w1*a.w + w2*b.w;
    *(float4*)(out + (size_t)s * HID + h) = o;
}

extern "C" void kernel_launch(void* const* d_in, const int* in_sizes, int n_in,
                              void* d_out, int out_size) {
    const float* hid = (const float*)d_in[0];
    const float* gw  = (const float*)d_in[1];
    const float* wg  = (const float*)d_in[2];
    const float* wu  = (const float*)d_in[3];
    const float* wd  = (const float*)d_in[4];
    float* out = (float*)d_out;

    cudaFuncSetAttribute(gemm1_kernel, cudaFuncAttributeMaxDynamicSharedMemorySize, G1_DS);
    cudaFuncSetAttribute(gemm2_kernel, cudaFuncAttributeMaxDynamicSharedMemorySize, G2_DS);

    __half* wgt; cudaGetSymbolAddress((void**)&wgt, g_WGt);
    __half* wut; cudaGetSymbolAddress((void**)&wut, g_WUt);
    __half* wdt; cudaGetSymbolAddress((void**)&wdt, g_WDt);

    transpose_kernel<<<dim3(TWOF / 32, HID / 32, NE), 256>>>(wg, wgt, HID, TWOF);
    transpose_kernel<<<dim3(FF / 32, HID / 32, NE), 256>>>(wu, wut, HID, FF);
    transpose_kernel<<<dim3(HID / 32, FF / 32, NE), 256>>>(wd, wdt, FF, HID);
    router_kernel<<<S_TOK, 256>>>(hid, gw);
    scan_kernel<<<1, 256>>>();
    gemm1_kernel<<<dim3(CAP / 64, FF / 64, NE), 256, G1_DS>>>();
    gemm2_kernel<<<dim3(CAP / 128, HID / 128, NE), 256, G2_DS>>>();
    combine_kernel<<<S_TOK, 256>>>(out);
}

// round 15
// speedup vs baseline: 1.4429x; 1.0202x over previous
#include <cuda_runtime.h>
#include <cuda_fp16.h>
#include <cstdint>
#include <math.h>

#define S_TOK 4096
#define HID   1024
#define FF    4096
#define NE    8
#define CAP   1280
#define TWOF  8192

// pair-index permutation within 8-pair (16-half) blocks: [0,4,1,5,2,6,3,7]
#define PERM8(k) (((k) & ~7) | ((((k) & 3)) << 1) | (((k) >> 2) & 1))

__device__ int   g_e1[S_TOK], g_e2[S_TOK];
__device__ float g_p1[S_TOK], g_p2[S_TOK];
__device__ int   g_slot1[S_TOK], g_slot2[S_TOK];
__device__ float g_fw1[S_TOK], g_fw2[S_TOK];
__device__ int   g_slot_token[NE * CAP];
__device__ int   g_cnt[NE];

__device__ __half g_TOK [(size_t)S_TOK * HID];      // fp16, H pair-permuted
__device__ __half g_WGt [(size_t)NE * TWOF * HID];  // [E][2F][H] fp16, H perm
__device__ __half g_WUt [(size_t)NE * FF * HID];    // [E][F][H]  fp16, H perm
__device__ __half g_WDt [(size_t)NE * HID * FF];    // [E][H][F]  fp16, F perm
__device__ __half g_ACT [(size_t)NE * CAP * FF];    // fp16, F pair-permuted
__device__ float  g_EOUT[(size_t)NE * CAP * HID];

// ---------- helpers ----------
__device__ __forceinline__ void mma_f16(float* d, const uint32_t* a, const uint32_t* b) {
    asm("mma.sync.aligned.m16n8k16.row.col.f32.f16.f16.f32 "
        "{%0,%1,%2,%3}, {%4,%5,%6,%7}, {%8,%9}, {%0,%1,%2,%3};"
        : "+f"(d[0]), "+f"(d[1]), "+f"(d[2]), "+f"(d[3])
        : "r"(a[0]), "r"(a[1]), "r"(a[2]), "r"(a[3]), "r"(b[0]), "r"(b[1]));
}
__device__ __forceinline__ void cp16(uint32_t sa, const void* ga, bool ok) {
    int sz = ok ? 16 : 0;
    asm volatile("cp.async.cg.shared.global [%0], [%1], 16, %2;\n" :: "r"(sa), "l"(ga), "r"(sz));
}
#define CP_COMMIT() asm volatile("cp.async.commit_group;\n" ::: "memory")
template <int N> __device__ __forceinline__ void cp_wait() {
    asm volatile("cp.async.wait_group %0;" :: "n"(N) : "memory");
}

// ========== 1) fused prep: router + 3 weight transposes in ONE launch ==========
// blocks [0, 4096)                      : router (token = b)
// blocks [4096, 4096+65536)             : w_gate transpose
// next 32768                            : w_up transpose
// next 32768                            : w_down transpose
#define PREP_WG_BLKS 65536
#define PREP_WU_BLKS 32768
#define PREP_WD_BLKS 32768
#define PREP_BLKS (S_TOK + PREP_WG_BLKS + PREP_WU_BLKS + PREP_WD_BLKS)

__device__ __forceinline__ void do_transpose(const float* __restrict__ src,
                                             __half* __restrict__ dst,
                                             int K, int N, int kt, int nt,
                                             float* sh) {
    float (*t)[33] = (float(*)[33])sh;
    const int k0 = kt * 32, n0 = nt * 32;
    const int tx = threadIdx.x & 31, ty = threadIdx.x >> 5;   // 32 x 8
#pragma unroll
    for (int j = 0; j < 4; j++)
        t[ty + j * 8][tx] = src[(size_t)(k0 + ty + j * 8) * N + n0 + tx];
    __syncthreads();
    // write phase: 512 half2 (32 rows x 16 pairs), 2 per thread
#pragma unroll
    for (int j = 0; j < 2; j++) {
        int idx = threadIdx.x + j * 256;
        int row = idx >> 4;          // n-local 0..31
        int p = idx & 15;            // k-pair 0..15
        __half2 v = __floats2half2_rn(t[2 * p][row], t[2 * p + 1][row]);
        size_t base = ((size_t)(n0 + row) * K + k0) >> 1;
        ((__half2*)dst)[base + PERM8(p)] = v;
    }
}

__global__ void __launch_bounds__(256) prep_kernel(const float* __restrict__ hid,
                                                   const float* __restrict__ gw,
                                                   const float* __restrict__ wg,
                                                   const float* __restrict__ wu,
                                                   const float* __restrict__ wd) {
    __shared__ float sh[NE * 256];   // router: red[8][256]; transpose: t[32][33] (1056 floats)
    int b = blockIdx.x;
    const int tid = threadIdx.x;

    if (b < S_TOK) {
        // ----- router (arithmetic identical to prior rounds) -----
        int s = b;
        float acc[NE];
#pragma unroll
        for (int e = 0; e < NE; e++) acc[e] = 0.f;
        const float* row = hid + (size_t)s * HID;
        __half2* tdst = (__half2*)(g_TOK + (size_t)s * HID);
#pragma unroll
        for (int it = 0; it < 2; it++) {
            int p = tid + it * 256;              // pair index (h = 2p, 2p+1)
            float2 x = *(const float2*)(row + 2 * p);
            tdst[PERM8(p)] = __floats2half2_rn(x.x, x.y);
            float4 lo = *(const float4*)(gw + (size_t)(2 * p) * NE);
            float4 hi4 = *(const float4*)(gw + (size_t)(2 * p) * NE + 4);
            acc[0] += x.x*lo.x; acc[1] += x.x*lo.y; acc[2] += x.x*lo.z; acc[3] += x.x*lo.w;
            acc[4] += x.x*hi4.x; acc[5] += x.x*hi4.y; acc[6] += x.x*hi4.z; acc[7] += x.x*hi4.w;
            lo = *(const float4*)(gw + (size_t)(2 * p + 1) * NE);
            hi4 = *(const float4*)(gw + (size_t)(2 * p + 1) * NE + 4);
            acc[0] += x.y*lo.x; acc[1] += x.y*lo.y; acc[2] += x.y*lo.z; acc[3] += x.y*lo.w;
            acc[4] += x.y*hi4.x; acc[5] += x.y*hi4.y; acc[6] += x.y*hi4.z; acc[7] += x.y*hi4.w;
        }
#pragma unroll
        for (int e = 0; e < NE; e++) sh[e * 256 + tid] = acc[e];
        __syncthreads();
        for (int st = 128; st > 0; st >>= 1) {
            if (tid < st)
#pragma unroll
                for (int e = 0; e < NE; e++) sh[e * 256 + tid] += sh[e * 256 + tid + st];
            __syncthreads();
        }
        if (tid == 0) {
            float l[NE], p[NE];
#pragma unroll
            for (int e = 0; e < NE; e++) l[e] = sh[e * 256];
            float m = l[0];
#pragma unroll
            for (int e = 1; e < NE; e++) m = fmaxf(m, l[e]);
            float se = 0.f;
#pragma unroll
            for (int e = 0; e < NE; e++) { p[e] = expf(l[e] - m); se += p[e]; }
            float inv = 1.f / se;
#pragma unroll
            for (int e = 0; e < NE; e++) p[e] *= inv;
            int t1 = 0; float b1 = p[0];
            for (int e = 1; e < NE; e++) if (p[e] > b1) { b1 = p[e]; t1 = e; }
            int t2 = (t1 == 0) ? 1 : 0; float b2 = p[t2];
            for (int e = 0; e < NE; e++) if (e != t1 && p[e] > b2) { b2 = p[e]; t2 = e; }
            g_e1[s] = t1; g_e2[s] = t2; g_p1[s] = b1; g_p2[s] = b2;
        }
        return;
    }
    b -= S_TOK;
    if (b < PREP_WG_BLKS) {          // w_gate: K=HID, N=TWOF; 256 nt x 32 kt per expert
        int e = b >> 13, r = b & 8191;
        int nt = r & 255, kt = r >> 8;
        do_transpose(wg + (size_t)e * HID * TWOF, g_WGt + (size_t)e * TWOF * HID,
                     HID, TWOF, kt, nt, sh);
        return;
    }
    b -= PREP_WG_BLKS;
    if (b < PREP_WU_BLKS) {          // w_up: K=HID, N=FF; 128 nt x 32 kt
        int e = b >> 12, r = b & 4095;
        int nt = r & 127, kt = r >> 7;
        do_transpose(wu + (size_t)e * HID * FF, g_WUt + (size_t)e * FF * HID,
                     HID, FF, kt, nt, sh);
        return;
    }
    b -= PREP_WU_BLKS;
    {                                 // w_down: K=FF, N=HID; 32 nt x 128 kt
        int e = b >> 12, r = b & 4095;
        int nt = r & 31, kt = r >> 5;
        do_transpose(wd + (size_t)e * FF * HID, g_WDt + (size_t)e * HID * FF,
                     FF, HID, kt, nt, sh);
    }
}

// ---------- 2) scan ----------
__global__ void __launch_bounds__(256) scan_kernel() {
    __shared__ unsigned char se1[S_TOK], se2[S_TOK];
    __shared__ int c1[256][NE], c2[256][NE];
    int tid = threadIdx.x;
    for (int i = tid; i < NE * CAP; i += 256) g_slot_token[i] = -1;
    for (int i = tid; i < S_TOK; i += 256) {
        se1[i] = (unsigned char)g_e1[i];
        se2[i] = (unsigned char)g_e2[i];
    }
    __syncthreads();
    int lc1[NE], lc2[NE];
#pragma unroll
    for (int e = 0; e < NE; e++) { lc1[e] = 0; lc2[e] = 0; }
    for (int j = 0; j < 16; j++) {
        int s = tid * 16 + j;
        lc1[se1[s]]++; lc2[se2[s]]++;
    }
#pragma unroll
    for (int e = 0; e < NE; e++) { c1[tid][e] = lc1[e]; c2[tid][e] = lc2[e]; }
    __syncthreads();
    if (tid < NE) {
        int e = tid, run = 0;
        for (int t = 0; t < 256; t++) { int v = c1[t][e]; c1[t][e] = run; run += v; }
        int run2 = run;  // rank2 base = PRE-capacity top1 total (matches reference)
        for (int t = 0; t < 256; t++) { int v = c2[t][e]; c2[t][e] = run2; run2 += v; }
        g_cnt[e] = run2 < CAP ? run2 : CAP;
    }
    __syncthreads();
    int o1[NE], o2[NE];
#pragma unroll
    for (int e = 0; e < NE; e++) { o1[e] = c1[tid][e]; o2[e] = c2[tid][e]; }
    for (int j = 0; j < 16; j++) {
        int s = tid * 16 + j;
        int e1 = se1[s], e2 = se2[s];
        int r1 = o1[e1]++, r2 = o2[e2]++;
        if (r1 < CAP) { int sl = e1*CAP+r1; g_slot1[s]=sl; g_slot_token[sl]=s; g_fw1[s]=g_p1[s]; }
        else          { g_slot1[s]=0; g_fw1[s]=0.f; }
        if (r2 < CAP) { int sl = e2*CAP+r2; g_slot2[s]=sl; g_slot_token[sl]=s; g_fw2[s]=g_p2[s]; }
        else          { g_slot2[s]=0; g_fw2[s]=0.f; }
    }
}

// ========== 3) fused GEMM1 + SwiGLU (fp16 m16n8k16, asymmetric A2/B3 pipeline) ==========
// Block 64m x 64f, 256 thr (8 warps 2m x 4n), warp tile 32m x 16f per matrix.
// A: 2 buffers of 64 rows x 160B; B: 3 buffers of 3x64 rows x 160B. 112.6KB -> 2 CTAs/SM.
#define G1_ROWB 160
#define G1_ABUF 10240                    // 64*160
#define G1_BMAT 10240                    // 64*160
#define G1_BSTG 30720                    // 3 mats
#define G1_BOFF 20480                    // after 2 A buffers
#define G1_DS   (G1_BOFF + 3 * G1_BSTG)  // 112640 B
#define G1_NK   (HID / 64)               // 16

__global__ void __launch_bounds__(256, 2) gemm1_kernel() {
    extern __shared__ char raw[];
    __shared__ int stok[64];

    const int e = blockIdx.z, m0 = blockIdx.x * 64, f0 = blockIdx.y * 64;
    if (m0 >= g_cnt[e]) return;
    const int tid = threadIdx.x;

    if (tid < 64) stok[tid] = g_slot_token[e * CAP + m0 + tid];
    __syncthreads();

    const __half* W0 = g_WGt + (size_t)e * TWOF * HID + (size_t)f0 * HID;        // x1 rows
    const __half* W1 = g_WGt + (size_t)e * TWOF * HID + (size_t)(FF + f0) * HID; // x2 rows
    const __half* W2 = g_WUt + (size_t)e * FF * HID + (size_t)f0 * HID;          // u rows

    const uint32_t smb = (uint32_t)__cvta_generic_to_shared(raw);

    // A: 2 chunks/thread (rows ar, ar+32), 8 chunks(16B)/row
    const int ar = tid >> 3, ac = tid & 7;
    const int t0 = stok[ar], t1 = stok[ar + 32];
    const bool aok0 = (t0 >= 0), aok1 = (t1 >= 0);
    const __half* as0 = g_TOK + (size_t)(t0 < 0 ? 0 : t0) * HID + ac * 8;
    const __half* as1 = g_TOK + (size_t)(t1 < 0 ? 0 : t1) * HID + ac * 8;
    const uint32_t ad0 = ar * G1_ROWB + ac * 16;
    const uint32_t ad1 = (ar + 32) * G1_ROWB + ac * 16;
    // B: rows ar, ar+32 per matrix
    const uint32_t bd0 = ar * G1_ROWB + ac * 16;
    const uint32_t bd1 = (ar + 32) * G1_ROWB + ac * 16;
    const __half* ws0[3] = { W0 + (size_t)ar * HID + ac * 8,
                             W1 + (size_t)ar * HID + ac * 8,
                             W2 + (size_t)ar * HID + ac * 8 };
    const __half* ws1[3] = { W0 + (size_t)(ar + 32) * HID + ac * 8,
                             W1 + (size_t)(ar + 32) * HID + ac * 8,
                             W2 + (size_t)(ar + 32) * HID + ac * 8 };

#define G1_LDA(st, kt) do {                                                    \
    uint32_t _sb = smb + (uint32_t)(st) * G1_ABUF;                             \
    cp16(_sb + ad0, as0 + (kt), aok0);                                         \
    cp16(_sb + ad1, as1 + (kt), aok1);                                         \
    CP_COMMIT(); } while (0)
#define G1_LDB(st, kt) do {                                                    \
    uint32_t _sb = smb + G1_BOFF + (uint32_t)(st) * G1_BSTG;                   \
    _Pragma("unroll") for (int j = 0; j < 3; j++) {                            \
        cp16(_sb + bd0 + j * G1_BMAT, ws0[j] + (kt), true);                    \
        cp16(_sb + bd1 + j * G1_BMAT, ws1[j] + (kt), true);                    \
    }                                                                          \
    CP_COMMIT(); } while (0)

    float acc[3][2][2][4];
#pragma unroll
    for (int j = 0; j < 3; j++)
#pragma unroll
        for (int mt = 0; mt < 2; mt++)
#pragma unroll
            for (int nt = 0; nt < 2; nt++)
#pragma unroll
                for (int i = 0; i < 4; i++) acc[j][mt][nt][i] = 0.f;

    const int warp = tid >> 5, lane = tid & 31;
    const int warp_m = warp >> 2, warp_n = warp & 3;   // 2m x 4n
    const int g = lane >> 2, c = lane & 3;

    // prologue: B(0), A(0), B(1)  -> pending groups {B0, A0, B1}
    G1_LDB(0, 0);
    G1_LDA(0, 0);
    G1_LDB(1, 64);

    int bs = 0;   // B stage of iter i
    for (int i = 0; i < G1_NK; i++) {
        cp_wait<1>();          // completes B(i), A(i); leaves B(i+1) in flight
        __syncthreads();
        if (i + 1 < G1_NK) G1_LDA((i + 1) & 1, (i + 1) * 64); else CP_COMMIT();
        {
            int ip2 = i + 2;
            int bs2 = bs + 2; if (bs2 >= 3) bs2 -= 3;
            if (ip2 < G1_NK) G1_LDB(bs2, ip2 * 64); else CP_COMMIT();
        }

        const char* Ab = raw + (i & 1) * G1_ABUF;
        const char* Bb = raw + G1_BOFF + bs * G1_BSTG;
        if (++bs == 3) bs = 0;
#pragma unroll
        for (int s = 0; s < 4; s++) {          // 4 x k16
            const int off = s * 32 + c * 8;
            uint32_t a[2][4];
#pragma unroll
            for (int mt = 0; mt < 2; mt++) {
                int r0 = warp_m * 32 + mt * 16;
                uint2 v0 = *(const uint2*)(Ab + (r0 + g) * G1_ROWB + off);
                uint2 v1 = *(const uint2*)(Ab + (r0 + g + 8) * G1_ROWB + off);
                a[mt][0] = v0.x; a[mt][1] = v1.x; a[mt][2] = v0.y; a[mt][3] = v1.y;
            }
#pragma unroll
            for (int j = 0; j < 3; j++) {
                uint32_t b[2][2];
#pragma unroll
                for (int nt = 0; nt < 2; nt++) {
                    int n = warp_n * 16 + nt * 8 + g;
                    uint2 vb = *(const uint2*)(Bb + j * G1_BMAT + n * G1_ROWB + off);
                    b[nt][0] = vb.x; b[nt][1] = vb.y;
                }
#pragma unroll
                for (int mt = 0; mt < 2; mt++)
#pragma unroll
                    for (int nt = 0; nt < 2; nt++)
                        mma_f16(acc[j][mt][nt], a[mt], b[nt]);
            }
        }
    }

    // epilogue: act = x1*silu(x2)*u -> fp16, F pair-permuted
#pragma unroll
    for (int mt = 0; mt < 2; mt++)
#pragma unroll
        for (int nt = 0; nt < 2; nt++) {
            int row = m0 + warp_m * 32 + mt * 16 + g;
            int colp = (f0 + warp_n * 16 + nt * 8 + c * 2) >> 1;   // pair index
            float o[4];
#pragma unroll
            for (int i = 0; i < 4; i++) {
                float x1 = acc[0][mt][nt][i];
                float x2 = acc[1][mt][nt][i];
                float u  = acc[2][mt][nt][i];
                o[i] = x1 * (x2 / (1.f + __expf(-x2))) * u;
            }
            ((__half2*)(g_ACT + ((size_t)e * CAP + row) * FF))[PERM8(colp)] =
                __floats2half2_rn(o[0], o[1]);
            ((__half2*)(g_ACT + ((size_t)e * CAP + row + 8) * FF))[PERM8(colp)] =
                __floats2half2_rn(o[2], o[3]);
        }
#undef G1_LDA
#undef G1_LDB
}

// ========== 4) GEMM2: ACT x w_down^T -> EOUT (fp16, asymmetric A2/B3 pipeline) ==========
// Block 128m x 128n, 256 thr (8 warps 2m x 4n), warp tile 64m x 32n. 100KB -> 2 CTAs/SM.
#define G2_ROWB 160
#define G2_ABUF 20480                    // 128*160
#define G2_BBUF 20480
#define G2_BOFF 40960
#define G2_DS   (G2_BOFF + 3 * G2_BBUF)  // 102400 B
#define G2_NK   (FF / 64)                // 64

__global__ void __launch_bounds__(256, 2) gemm2_kernel() {
    extern __shared__ char raw[];

    const int e = blockIdx.z, m0 = blockIdx.x * 128, n0 = blockIdx.y * 128;
    if (m0 >= g_cnt[e]) return;
    const int tid = threadIdx.x;

    const __half* A = g_ACT + (size_t)(e * CAP + m0) * FF;
    const __half* B = g_WDt + (size_t)e * HID * FF + (size_t)n0 * FF;
    float* Cout = g_EOUT + (size_t)e * CAP * HID + n0;

    const uint32_t smb = (uint32_t)__cvta_generic_to_shared(raw);
    const int ar = tid >> 3, ac = tid & 7;   // rows ar + q*32, 8 chunks/row

#define G2_LDA(st, kt) do {                                                      \
    uint32_t _sb = smb + (uint32_t)(st) * G2_ABUF;                               \
    _Pragma("unroll") for (int q = 0; q < 4; q++)                                \
        cp16(_sb + (ar + q * 32) * G2_ROWB + ac * 16,                            \
             A + (size_t)(ar + q * 32) * FF + (kt) + ac * 8, true);              \
    CP_COMMIT(); } while (0)
#define G2_LDB(st, kt) do {                                                      \
    uint32_t _sb = smb + G2_BOFF + (uint32_t)(st) * G2_BBUF;                     \
    _Pragma("unroll") for (int q = 0; q < 4; q++)                                \
        cp16(_sb + (ar + q * 32) * G2_ROWB + ac * 16,                            \
             B + (size_t)(ar + q * 32) * FF + (kt) + ac * 8, true);              \
    CP_COMMIT(); } while (0)

    float acc[4][4][4];
#pragma unroll
    for (int mt = 0; mt < 4; mt++)
#pragma unroll
        for (int nt = 0; nt < 4; nt++)
#pragma unroll
            for (int i = 0; i < 4; i++) acc[mt][nt][i] = 0.f;

    const int warp = tid >> 5, lane = tid & 31;
    const int warp_m = warp >> 2, warp_n = warp & 3;   // 2m x 4n
    const int g = lane >> 2, c = lane & 3;

    // prologue: B(0), A(0), B(1)
    G2_LDB(0, 0);
    G2_LDA(0, 0);
    G2_LDB(1, 64);

    int bs = 0;
    for (int i = 0; i < G2_NK; i++) {
        cp_wait<1>();
        __syncthreads();
        if (i + 1 < G2_NK) G2_LDA((i + 1) & 1, (i + 1) * 64); else CP_COMMIT();
        {
            int ip2 = i + 2;
            int bs2 = bs + 2; if (bs2 >= 3) bs2 -= 3;
            if (ip2 < G2_NK) G2_LDB(bs2, ip2 * 64); else CP_COMMIT();
        }

        const char* Ab = raw + (i & 1) * G2_ABUF;
        const char* Bb = raw + G2_BOFF + bs * G2_BBUF;
        if (++bs == 3) bs = 0;
#pragma unroll
        for (int s = 0; s < 4; s++) {
            const int off = s * 32 + c * 8;
            uint32_t a[4][4];
#pragma unroll
            for (int mt = 0; mt < 4; mt++) {
                int r0 = warp_m * 64 + mt * 16;
                uint2 v0 = *(const uint2*)(Ab + (r0 + g) * G2_ROWB + off);
                uint2 v1 = *(const uint2*)(Ab + (r0 + g + 8) * G2_ROWB + off);
                a[mt][0] = v0.x; a[mt][1] = v1.x; a[mt][2] = v0.y; a[mt][3] = v1.y;
            }
#pragma unroll
            for (int nt = 0; nt < 4; nt++) {
                int n = warp_n * 32 + nt * 8 + g;
                uint2 vb = *(const uint2*)(Bb + n * G2_ROWB + off);
                uint32_t b[2] = { vb.x, vb.y };
#pragma unroll
                for (int mt = 0; mt < 4; mt++)
                    mma_f16(acc[mt][nt], a[mt], b);
            }
        }
    }

#pragma unroll
    for (int mt = 0; mt < 4; mt++)
#pragma unroll
        for (int nt = 0; nt < 4; nt++) {
            int row = m0 + warp_m * 64 + mt * 16 + g;
            int col = warp_n * 32 + nt * 8 + c * 2;
            *(float2*)(Cout + (size_t)row * HID + col)       = make_float2(acc[mt][nt][0], acc[mt][nt][1]);
            *(float2*)(Cout + (size_t)(row + 8) * HID + col) = make_float2(acc[mt][nt][2], acc[mt][nt][3]);
        }
#undef G2_LDA
#undef G2_LDB
}

// ---------- 5) combine ----------
__global__ void __launch_bounds__(256) combine_kernel(float* __restrict__ out) {
    int s = blockIdx.x, h = threadIdx.x * 4;
    int sl1 = g_slot1[s], sl2 = g_slot2[s];
    float w1 = g_fw1[s], w2 = g_fw2[s];
    float4 a = *(const float4*)(g_EOUT + (size_t)sl1 * HID + h);
    float4 b = *(const float4*)(g_EOUT + (size_t)sl2 * HID + h);
    float4 o;
    o.x = w1*a.x + w2*b.x; o.y = w1*a.y + w2*b.y;
    o.z = w1*a.z + w2*b.z; o.w = w1*a.w + w2*b.w;
    *(float4*)(out + (size_t)s * HID + h) = o;
}

extern "C" void kernel_launch(void* const* d_in, const int* in_sizes, int n_in,
                              void* d_out, int out_size) {
    const float* hid = (const float*)d_in[0];
    const float* gw  = (const float*)d_in[1];
    const float* wg  = (const float*)d_in[2];
    const float* wu  = (const float*)d_in[3];
    const float* wd  = (const float*)d_in[4];
    float* out = (float*)d_out;

    cudaFuncSetAttribute(gemm1_kernel, cudaFuncAttributeMaxDynamicSharedMemorySize, G1_DS);
    cudaFuncSetAttribute(gemm2_kernel, cudaFuncAttributeMaxDynamicSharedMemorySize, G2_DS);

    prep_kernel<<<PREP_BLKS, 256>>>(hid, gw, wg, wu, wd);
    scan_kernel<<<1, 256>>>();
    gemm1_kernel<<<dim3(CAP / 64, FF / 64, NE), 256, G1_DS>>>();
    gemm2_kernel<<<dim3(CAP / 128, HID / 128, NE), 256, G2_DS>>>();
    combine_kernel<<<S_TOK, 256>>>(out);
}